// round 12
// baseline (speedup 1.0000x reference)
#include <cuda_runtime.h>
#include <cuda_bf16.h>
#include <cstdint>

// ---------------- scratch (static __device__ — no allocation allowed) ----------------
__device__ float g_Pa[(size_t)65536 * 256];   // h_node @ W0[0:128]
__device__ float g_Pb[(size_t)65536 * 256];   // h_node @ W0[128:256]
__device__ int   g_mode64;                    // 1 if edge_index is int64
// Pre-split bf16 weights, chunked+swizzled: [(l*8+kc)][hi 16KB | lo 16KB]
__device__ __align__(128) unsigned char g_WblobB[(size_t)8 * 8 * 2 * 16384];

__device__ __forceinline__ float leaky(float v) { return fmaxf(v, 0.01f * v); }

// ================= PTX helpers (base sm_90 features only — NO tcgen05) =================
__device__ __forceinline__ uint32_t smem_u32(const void* p) {
    uint32_t a;
    asm("{ .reg .u64 t; cvta.to.shared.u64 t, %1; cvt.u32.u64 %0, t; }" : "=r"(a) : "l"(p));
    return a;
}
#define MBAR_INIT(a, n) asm volatile("mbarrier.init.shared.b64 [%0], %1;" :: "r"(a), "r"((uint32_t)(n)) : "memory")
#define MBAR_EXPECT_TX(a, n) asm volatile("mbarrier.arrive.expect_tx.shared.b64 _, [%0], %1;" :: "r"(a), "r"((uint32_t)(n)) : "memory")
#define MBAR_ARRIVE(a) asm volatile("mbarrier.arrive.shared.b64 _, [%0];" :: "r"(a) : "memory")

#define MBAR_WAIT(mbar, par) do { \
    uint32_t _m = (mbar); uint32_t _p = (par); uint32_t _d; \
    asm volatile("{ .reg .pred p; mbarrier.try_wait.parity.acquire.cta.shared::cta.b64 p, [%1], %2; selp.b32 %0,1,0,p; }" \
        : "=r"(_d) : "r"(_m), "r"(_p) : "memory"); \
    if (!_d) { \
        asm volatile("{ .reg .pred P1; WL%=: mbarrier.try_wait.parity.acquire.cta.shared::cta.b64 P1, [%0], %1, 0x989680; @P1 bra.uni WD%=; bra.uni WL%=; WD%=: }" \
            :: "r"(_m), "r"(_p) : "memory"); \
    } \
} while (0)

__device__ __forceinline__ void bulk_g2s(uint32_t dst, const void* src, uint32_t bytes, uint32_t mbar) {
    asm volatile("cp.async.bulk.shared::cta.global.mbarrier::complete_tx::bytes [%0], [%1], %2, [%3];"
        :: "r"(dst), "l"(src), "r"(bytes), "r"(mbar) : "memory");
}

__device__ __forceinline__ void ldsm4(uint32_t* r, uint32_t addr) {
    asm volatile("ldmatrix.sync.aligned.m8n8.x4.shared.b16 {%0,%1,%2,%3}, [%4];"
        : "=r"(r[0]), "=r"(r[1]), "=r"(r[2]), "=r"(r[3]) : "r"(addr));
}
__device__ __forceinline__ void mma4(float (&d)[4], const uint32_t* a, uint32_t b0, uint32_t b1) {
    asm volatile("mma.sync.aligned.m16n8k16.row.col.f32.bf16.bf16.f32 "
                 "{%0,%1,%2,%3},{%4,%5,%6,%7},{%8,%9},{%0,%1,%2,%3};"
                 : "+f"(d[0]), "+f"(d[1]), "+f"(d[2]), "+f"(d[3])
                 : "r"(a[0]), "r"(a[1]), "r"(a[2]), "r"(a[3]), "r"(b0), "r"(b1));
}

// ---------------- dtype detection for edge_index ----------------
__global__ void detect_kernel(const unsigned int* ei, int n_scan) {
    __shared__ int nz;
    if (threadIdx.x == 0) nz = 0;
    __syncthreads();
    int loc = 0;
    for (int i = threadIdx.x; i < n_scan; i += blockDim.x)
        if (ei[2 * i + 1] != 0u) loc = 1;
    if (loc) atomicExch(&nz, 1);
    __syncthreads();
    if (threadIdx.x == 0) g_mode64 = (nz == 0) ? 1 : 0;
}

// ---------------- weight prep: bf16 hi/lo, [n][k32-chunk] rows of 64B, XOR swizzle ----------------
__global__ void prep_w(const float* __restrict__ W_mid) {
    int idx = blockIdx.x * blockDim.x + threadIdx.x;  // 8*65536
    if (idx >= 8 * 65536) return;
    int l = idx >> 16, rem = idx & 65535, k = rem >> 8, n = rem & 255;
    float w = W_mid[idx];
    __nv_bfloat16 hi = __float2bfloat16(w);
    __nv_bfloat16 lo = __float2bfloat16(w - __bfloat162float(hi));
    int kc = k >> 5, kk = k & 31;
    int c = kk >> 3, phys = c ^ ((n >> 1) & 3);
    size_t off = ((size_t)(l * 8 + kc) * 2) * 16384 + (size_t)n * 64 + phys * 16 + (kk & 7) * 2;
    *(__nv_bfloat16*)(g_WblobB + off) = hi;
    *(__nv_bfloat16*)(g_WblobB + off + 16384) = lo;
}

// ---------------- node kernel (fp32): h = leaky(x@Wx+bx); Pa = h@W0a; Pb = h@W0b ----------------
__global__ __launch_bounds__(256, 1) void node_kernel(
    const float* __restrict__ x, const float* __restrict__ Wx,
    const float* __restrict__ bx, const float* __restrict__ W0, int N)
{
    extern __shared__ float sm[];
    float* Xs = sm;
    float* Hs = Xs + 64 * 256;
    float* Wt = Hs + 64 * 132;

    const int tid = threadIdx.x;
    const int n0 = blockIdx.x * 64;
    {
        const float4* xg = (const float4*)x + (size_t)n0 * 64;
        float4* Xs4 = (float4*)Xs;
#pragma unroll
        for (int i = 0; i < 16; i++) Xs4[tid + 256 * i] = xg[tid + 256 * i];
    }
    __syncthreads();
    {
        const int cg = tid & 15, rg = tid >> 4;
        const int c0 = cg * 8, r0 = rg * 4;
        float acc[4][8];
#pragma unroll
        for (int i = 0; i < 4; i++)
#pragma unroll
            for (int j = 0; j < 8; j++) acc[i][j] = 0.f;
        for (int kc = 0; kc < 256; kc += 16) {
            __syncthreads();
            const float4* wg = (const float4*)(Wx + kc * 128);
            float4* Wt4 = (float4*)Wt;
            Wt4[tid] = wg[tid];
            Wt4[tid + 256] = wg[tid + 256];
            __syncthreads();
#pragma unroll
            for (int k = 0; k < 16; k++) {
                float a[4];
#pragma unroll
                for (int i = 0; i < 4; i++) a[i] = Xs[(r0 + i) * 256 + kc + k];
                float4 w0 = ((float4*)Wt)[k * 32 + cg * 2];
                float4 w1 = ((float4*)Wt)[k * 32 + cg * 2 + 1];
#pragma unroll
                for (int i = 0; i < 4; i++) {
                    float av = a[i];
                    acc[i][0] += av * w0.x; acc[i][1] += av * w0.y;
                    acc[i][2] += av * w0.z; acc[i][3] += av * w0.w;
                    acc[i][4] += av * w1.x; acc[i][5] += av * w1.y;
                    acc[i][6] += av * w1.z; acc[i][7] += av * w1.w;
                }
            }
        }
        float bb[8];
#pragma unroll
        for (int j = 0; j < 8; j++) bb[j] = bx[c0 + j];
#pragma unroll
        for (int i = 0; i < 4; i++) {
            float o[8];
#pragma unroll
            for (int j = 0; j < 8; j++) o[j] = leaky(acc[i][j] + bb[j]);
            *(float4*)(Hs + (r0 + i) * 132 + c0)     = make_float4(o[0], o[1], o[2], o[3]);
            *(float4*)(Hs + (r0 + i) * 132 + c0 + 4) = make_float4(o[4], o[5], o[6], o[7]);
        }
    }
    {
        const int cg = tid & 31, rg = tid >> 5;
        const int c0 = cg * 8, r0 = rg * 8;
#pragma unroll 1
        for (int tab = 0; tab < 2; tab++) {
            const float* Wg = W0 + (size_t)tab * 128 * 256;
            float acc[8][8];
#pragma unroll
            for (int i = 0; i < 8; i++)
#pragma unroll
                for (int j = 0; j < 8; j++) acc[i][j] = 0.f;
            for (int kc = 0; kc < 128; kc += 16) {
                __syncthreads();
                const float4* wg4 = (const float4*)(Wg + kc * 256);
                float4* Wt4 = (float4*)Wt;
#pragma unroll
                for (int i = 0; i < 4; i++) Wt4[tid + 256 * i] = wg4[tid + 256 * i];
                __syncthreads();
#pragma unroll
                for (int k = 0; k < 16; k++) {
                    float a[8];
#pragma unroll
                    for (int i = 0; i < 8; i++) a[i] = Hs[(r0 + i) * 132 + kc + k];
                    float4 w0 = ((float4*)Wt)[k * 64 + cg * 2];
                    float4 w1 = ((float4*)Wt)[k * 64 + cg * 2 + 1];
#pragma unroll
                    for (int i = 0; i < 8; i++) {
                        float av = a[i];
                        acc[i][0] += av * w0.x; acc[i][1] += av * w0.y;
                        acc[i][2] += av * w0.z; acc[i][3] += av * w0.w;
                        acc[i][4] += av * w1.x; acc[i][5] += av * w1.y;
                        acc[i][6] += av * w1.z; acc[i][7] += av * w1.w;
                    }
                }
            }
            float* outp = tab ? g_Pb : g_Pa;
#pragma unroll
            for (int i = 0; i < 8; i++) {
                size_t base = (size_t)(n0 + r0 + i) * 256 + c0;
                *(float4*)(outp + base)     = make_float4(acc[i][0], acc[i][1], acc[i][2], acc[i][3]);
                *(float4*)(outp + base + 4) = make_float4(acc[i][4], acc[i][5], acc[i][6], acc[i][7]);
            }
        }
    }
}

// ================= HMMA edge kernel =================
// 128 edges/CTA, 512 threads (16 warps: 4x4 grid of 32x64 warp tiles).
// SMEM: A_hi [128][256]bf16 @0 (64KB), A_lo @65536 (64KB), W stages @131072 (2 x 32KB), misc @196608.
// A row = 512B = 32 x 16B chunks, swizzle: phys = chunk ^ (row&7).
// W chunk rows: [n][k32] 64B, swizzle: phys = c ^ ((n>>1)&3).
#define AH 0
#define AL 65536
#define WS 131072
#define MISC 196608
#define EDGE_SMEM 211968

__global__ __launch_bounds__(512, 1) void edge_kernel(
    const void* __restrict__ ei_raw, const float* __restrict__ edge_attr,
    const float* __restrict__ W0, const float* __restrict__ b0,
    const float* __restrict__ b_mid,
    const float* __restrict__ Wlast, const float* __restrict__ blast,
    float* __restrict__ out, int E)
{
    extern __shared__ char smem[];
    const uint32_t sb = smem_u32(smem);
    const int tid = threadIdx.x, lane = tid & 31, wid = tid >> 5;
    const int wr = wid >> 2, wc = wid & 3;   // 4 rows x 4 cols of warps
    const int e0 = blockIdx.x * 128;

    int* s_row = (int*)(smem + MISC);
    int* s_col = (int*)(smem + MISC + 512);
    const uint32_t mb = sb + MISC + 1024;
    const uint32_t fullb[2] = { mb, mb + 8 };
    const uint32_t freeb[2] = { mb + 16, mb + 24 };
    float* part  = (float*)(smem + MISC + 1536);   // [128][3]
    float* b_all = (float*)(smem + MISC + 4096);   // [8][256]
    float* wl_s  = (float*)(smem + MISC + 12288);  // [256][3]
    float* W0c_s = (float*)(smem + WS + 32768);    // [16][256] (staged in W stage 1, init only)
    float* ea_s  = (float*)(smem + WS + 49152);    // [128][16]

    if (tid == 0) {
        MBAR_INIT(fullb[0], 1); MBAR_INIT(fullb[1], 1);
        MBAR_INIT(freeb[0], 16); MBAR_INIT(freeb[1], 16);
    }
    // ---- stage indices / ea / W0c / biases / Wlast / zero partials ----
    if (tid < 128) {
        long long e = (long long)e0 + tid;
        int r = 0, c = 0;
        if (e < E) {
            if (g_mode64) {
                const long long* p = (const long long*)ei_raw;
                r = (int)p[e]; c = (int)p[(long long)E + e];
            } else {
                const int* p = (const int*)ei_raw;
                r = p[e]; c = p[(long long)E + e];
            }
        }
        s_row[tid] = r; s_col[tid] = c;
    }
    {
        const float4* eg = (const float4*)edge_attr;
        long long base = (long long)e0 * 4;
        {
            long long gi = base + tid;
            float4 v = make_float4(0.f, 0.f, 0.f, 0.f);
            if (gi < (long long)E * 4) v = eg[gi];
            ((float4*)ea_s)[tid] = v;
        }
        const float4* wg = (const float4*)(W0 + 256 * 256);
#pragma unroll
        for (int t = 0; t < 2; t++) ((float4*)W0c_s)[tid + t * 512] = wg[tid + t * 512];
#pragma unroll
        for (int t = 0; t < 4; t++) b_all[tid + t * 512] = b_mid[tid + t * 512];
        for (int i = tid; i < 768; i += 512) wl_s[i] = Wlast[i];
        if (tid < 384) part[tid] = 0.f;
    }
    __syncthreads();
    if (tid == 0) {   // prefetch chunk 0 into stage 0 (W0c/ea sit in stage 1)
        MBAR_EXPECT_TX(fullb[0], 32768);
        bulk_g2s(sb + WS, g_WblobB, 32768, fullb[0]);
    }

    // ---- layer-0 init: A(0) = leaky(Pa[row] + Pb[col] + ea@W0c + b0) -> SMEM hi/lo ----
    {
        const int row = tid >> 2, hbase = (tid & 3) * 64;
        const int rn = s_row[row], cn = s_col[row];
        float ear[16];
#pragma unroll
        for (int k = 0; k < 16; k++) ear[k] = ea_s[row * 16 + k];
        const float* pa = g_Pa + (size_t)rn * 256 + hbase;
        const float* pb = g_Pb + (size_t)cn * 256 + hbase;
        const uint32_t rb = row * 512, rx = row & 7;
#pragma unroll 1
        for (int cc = 0; cc < 8; cc++) {
            const int n0 = hbase + cc * 8;
            float v[8];
            float4 A0 = *(const float4*)(pa + cc * 8), A1 = *(const float4*)(pa + cc * 8 + 4);
            float4 B0 = *(const float4*)(pb + cc * 8), B1 = *(const float4*)(pb + cc * 8 + 4);
            v[0] = A0.x + B0.x; v[1] = A0.y + B0.y; v[2] = A0.z + B0.z; v[3] = A0.w + B0.w;
            v[4] = A1.x + B1.x; v[5] = A1.y + B1.y; v[6] = A1.z + B1.z; v[7] = A1.w + B1.w;
#pragma unroll
            for (int k = 0; k < 16; k++) {
                float a = ear[k];
                const float4* wrow = (const float4*)(W0c_s + k * 256 + n0);
                float4 W0v = wrow[0], W1v = wrow[1];
                v[0] += a * W0v.x; v[1] += a * W0v.y; v[2] += a * W0v.z; v[3] += a * W0v.w;
                v[4] += a * W1v.x; v[5] += a * W1v.y; v[6] += a * W1v.z; v[7] += a * W1v.w;
            }
            const uint32_t off = rb + ((((uint32_t)n0 >> 3) ^ rx) << 4);
#pragma unroll
            for (int j = 0; j < 8; j += 2) {
                float v0 = leaky(v[j] + __ldg(&b0[n0 + j]));
                float v1 = leaky(v[j + 1] + __ldg(&b0[n0 + j + 1]));
                __nv_bfloat16 h0 = __float2bfloat16(v0), h1 = __float2bfloat16(v1);
                uint32_t hp = (uint32_t)__bfloat16_as_ushort(h0) | ((uint32_t)__bfloat16_as_ushort(h1) << 16);
                float r0 = v0 - __bfloat162float(h0), r1 = v1 - __bfloat162float(h1);
                __nv_bfloat16 g0 = __float2bfloat16(r0), g1 = __float2bfloat16(r1);
                uint32_t lp = (uint32_t)__bfloat16_as_ushort(g0) | ((uint32_t)__bfloat16_as_ushort(g1) << 16);
                *(uint32_t*)(smem + AH + off + j * 2) = hp;
                *(uint32_t*)(smem + AL + off + j * 2) = lp;
            }
        }
    }
    __syncthreads();
    if (tid == 0) {   // stage 1 free now: prefetch chunk 1
        MBAR_EXPECT_TX(fullb[1], 32768);
        bulk_g2s(sb + WS + 32768, g_WblobB + 32768, 32768, fullb[1]);
    }

    // ---- precomputed fragment addressing ----
    const uint32_t arow = wr * 32 + (lane & 15);
    const uint32_t abase = arow * 512;
    const uint32_t axor = arow & 7;
    const uint32_t akh = lane >> 4;
    const uint32_t bn = wc * 64 + (lane & 15);
    const uint32_t bbase = bn * 64;
    const uint32_t bxor = (bn >> 1) & 3;

    float d[2][8][4];

#pragma unroll 1
    for (int l = 0; l < 8; l++) {
#pragma unroll
        for (int i = 0; i < 2; i++)
#pragma unroll
            for (int j = 0; j < 8; j++)
#pragma unroll
                for (int q = 0; q < 4; q++) d[i][j][q] = 0.f;

#pragma unroll 1
        for (int kc = 0; kc < 8; kc++) {
            const int idx = l * 8 + kc, s = idx & 1, ph = (idx >> 1) & 1;
            MBAR_WAIT(fullb[s], ph);
            const uint32_t wbase = sb + WS + (uint32_t)s * 32768;
#pragma unroll
            for (int ks = 0; ks < 2; ks++) {
                const uint32_t achunk = (uint32_t)kc * 4 + (uint32_t)ks * 2 + akh;
                const uint32_t aoff = ((achunk ^ axor) << 4) + abase;
                const uint32_t c_ = (uint32_t)ks * 2 + akh;
                const uint32_t boff = ((c_ ^ bxor) << 4) + bbase;
                uint32_t afh[2][4], afl[2][4], bfr[4][4];
#pragma unroll
                for (int i = 0; i < 2; i++) ldsm4(afh[i], sb + AH + aoff + i * 8192);       // A_hi (rows +0,+16)
#pragma unroll
                for (int i = 0; i < 2; i++) ldsm4(afl[i], sb + AL + aoff + i * 8192);       // A_lo
#pragma unroll
                for (int g = 0; g < 4; g++) ldsm4(bfr[g], wbase + boff + g * 1024);         // B_hi
#pragma unroll
                for (int i = 0; i < 2; i++)
#pragma unroll
                    for (int g = 0; g < 4; g++) {
                        mma4(d[i][2 * g],     afh[i], bfr[g][0], bfr[g][2]);
                        mma4(d[i][2 * g + 1], afh[i], bfr[g][1], bfr[g][3]);
                    }
#pragma unroll
                for (int i = 0; i < 2; i++)
#pragma unroll
                    for (int g = 0; g < 4; g++) {
                        mma4(d[i][2 * g],     afl[i], bfr[g][0], bfr[g][2]);
                        mma4(d[i][2 * g + 1], afl[i], bfr[g][1], bfr[g][3]);
                    }
#pragma unroll
                for (int g = 0; g < 4; g++) ldsm4(bfr[g], wbase + 16384 + boff + g * 1024); // B_lo
#pragma unroll
                for (int i = 0; i < 2; i++)
#pragma unroll
                    for (int g = 0; g < 4; g++) {
                        mma4(d[i][2 * g],     afh[i], bfr[g][0], bfr[g][2]);
                        mma4(d[i][2 * g + 1], afh[i], bfr[g][1], bfr[g][3]);
                    }
            }
            __syncwarp();
            if (lane == 0) MBAR_ARRIVE(freeb[s]);
            if (tid == 0 && idx + 2 < 64) {
                MBAR_WAIT(freeb[s], ph);
                MBAR_EXPECT_TX(fullb[s], 32768);
                bulk_g2s(sb + WS + (uint32_t)s * 32768,
                         g_WblobB + (size_t)(idx + 2) * 32768, 32768, fullb[s]);
            }
        }

        if (l < 7) {
            // ---- epilogue: A(l+1) = leaky(D + b) -> SMEM hi/lo ----
            __syncthreads();
            const float* bs = b_all + l * 256;
#pragma unroll
            for (int i = 0; i < 2; i++) {
#pragma unroll
                for (int jn = 0; jn < 8; jn++) {
                    const int n = wc * 64 + jn * 8 + 2 * (lane & 3);
                    const float b0v = bs[n], b1v = bs[n + 1];
#pragma unroll
                    for (int h = 0; h < 2; h++) {
                        const int r = wr * 32 + i * 16 + (lane >> 2) + 8 * h;
                        float v0 = leaky(d[i][jn][2 * h]     + b0v);
                        float v1 = leaky(d[i][jn][2 * h + 1] + b1v);
                        __nv_bfloat16 h0 = __float2bfloat16(v0), h1 = __float2bfloat16(v1);
                        uint32_t hp = (uint32_t)__bfloat16_as_ushort(h0) | ((uint32_t)__bfloat16_as_ushort(h1) << 16);
                        float r0 = v0 - __bfloat162float(h0), r1 = v1 - __bfloat162float(h1);
                        __nv_bfloat16 g0 = __float2bfloat16(r0), g1 = __float2bfloat16(r1);
                        uint32_t lp = (uint32_t)__bfloat16_as_ushort(g0) | ((uint32_t)__bfloat16_as_ushort(g1) << 16);
                        const uint32_t off = (uint32_t)r * 512 + (((uint32_t)(n >> 3) ^ (uint32_t)(r & 7)) << 4) + (n & 7) * 2;
                        *(uint32_t*)(smem + AH + off) = hp;
                        *(uint32_t*)(smem + AL + off) = lp;
                    }
                }
            }
            __syncthreads();
        } else {
            // ---- logits: p[c] = sum_n leaky(D + b7[n]) * Wlast[n][c]; quad-shfl + smem atomics ----
            const float* bs = b_all + 7 * 256;
            float p[2][2][3];
#pragma unroll
            for (int i = 0; i < 2; i++)
#pragma unroll
                for (int h = 0; h < 2; h++)
#pragma unroll
                    for (int c = 0; c < 3; c++) p[i][h][c] = 0.f;
#pragma unroll
            for (int jn = 0; jn < 8; jn++) {
                const int n = wc * 64 + jn * 8 + 2 * (lane & 3);
                const float b0v = bs[n], b1v = bs[n + 1];
                const float w00 = wl_s[n * 3 + 0], w01 = wl_s[n * 3 + 1], w02 = wl_s[n * 3 + 2];
                const float w10 = wl_s[(n + 1) * 3 + 0], w11 = wl_s[(n + 1) * 3 + 1], w12 = wl_s[(n + 1) * 3 + 2];
#pragma unroll
                for (int i = 0; i < 2; i++)
#pragma unroll
                    for (int h = 0; h < 2; h++) {
                        float v0 = leaky(d[i][jn][2 * h]     + b0v);
                        float v1 = leaky(d[i][jn][2 * h + 1] + b1v);
                        p[i][h][0] += v0 * w00 + v1 * w10;
                        p[i][h][1] += v0 * w01 + v1 * w11;
                        p[i][h][2] += v0 * w02 + v1 * w12;
                    }
            }
#pragma unroll
            for (int i = 0; i < 2; i++)
#pragma unroll
                for (int h = 0; h < 2; h++)
#pragma unroll
                    for (int c = 0; c < 3; c++) {
                        float val = p[i][h][c];
                        val += __shfl_xor_sync(0xffffffffu, val, 1);
                        val += __shfl_xor_sync(0xffffffffu, val, 2);
                        if ((lane & 3) == 0) {
                            const int r = wr * 32 + i * 16 + (lane >> 2) + 8 * h;
                            atomicAdd(&part[r * 3 + c], val);
                        }
                    }
            __syncthreads();
            if (tid < 128) {
                float l0 = part[tid * 3 + 0] + __ldg(&blast[0]);
                float l1 = part[tid * 3 + 1] + __ldg(&blast[1]);
                float l2 = part[tid * 3 + 2] + __ldg(&blast[2]);
                float m = fmaxf(l0, fmaxf(l1, l2));
                float lse = m + logf(expf(l0 - m) + expf(l1 - m) + expf(l2 - m));
                long long e = (long long)e0 + tid;
                if (e < E) {
                    out[e * 3 + 0] = l0 - lse;
                    out[e * 3 + 1] = l1 - lse;
                    out[e * 3 + 2] = l2 - lse;
                }
            }
        }
    }
}

// ---------------- launch ----------------
extern "C" void kernel_launch(void* const* d_in, const int* in_sizes, int n_in,
                              void* d_out, int out_size)
{
    const float* x         = (const float*)d_in[0];
    const void*  ei        = d_in[1];
    const float* edge_attr = (const float*)d_in[2];
    const float* Wx        = (const float*)d_in[3];
    const float* bx        = (const float*)d_in[4];
    const float* W0        = (const float*)d_in[5];
    const float* b0        = (const float*)d_in[6];
    const float* W_mid     = (const float*)d_in[7];
    const float* b_mid     = (const float*)d_in[8];
    const float* Wlast     = (const float*)d_in[9];
    const float* blast     = (const float*)d_in[10];
    float* out = (float*)d_out;

    const int N = in_sizes[0] / 256;   // node count
    const int E = in_sizes[2] / 16;    // edge count

    const size_t smem_node = (size_t)(64 * 256 + 64 * 132 + 16 * 256) * 4;

    cudaFuncSetAttribute(node_kernel, cudaFuncAttributeMaxDynamicSharedMemorySize, (int)smem_node);
    cudaFuncSetAttribute(edge_kernel, cudaFuncAttributeMaxDynamicSharedMemorySize, EDGE_SMEM);

    int n_scan = E < 2048 ? E : 2048;
    detect_kernel<<<1, 256>>>((const unsigned int*)ei, n_scan);
    prep_w<<<(8 * 65536 + 255) / 256, 256>>>(W_mid);
    node_kernel<<<N / 64, 256, smem_node>>>(x, Wx, bx, W0, N);
    edge_kernel<<<(E + 127) / 128, 512, EDGE_SMEM>>>(ei, edge_attr, W0, b0,
                                                     b_mid, Wlast, blast, out, E);
}

// round 14
// speedup vs baseline: 1.0673x; 1.0673x over previous
#include <cuda_runtime.h>
#include <cuda_bf16.h>
#include <cstdint>

// ---------------- scratch (static __device__ — no allocation allowed) ----------------
__device__ float g_Pa[(size_t)65536 * 256];   // h_node @ W0[0:128]
__device__ float g_Pb[(size_t)65536 * 256];   // h_node @ W0[128:256]
__device__ int   g_mode64;                    // 1 if edge_index is int64
// Pre-split bf16 weights, chunked+swizzled: [(l*8+kc)][hi 16KB | lo 16KB]
__device__ __align__(128) unsigned char g_WblobB[(size_t)8 * 8 * 2 * 16384];

__device__ __forceinline__ float leaky(float v) { return fmaxf(v, 0.01f * v); }

// ================= PTX helpers (base sm_90 features only — NO tcgen05) =================
__device__ __forceinline__ uint32_t smem_u32(const void* p) {
    uint32_t a;
    asm("{ .reg .u64 t; cvta.to.shared.u64 t, %1; cvt.u32.u64 %0, t; }" : "=r"(a) : "l"(p));
    return a;
}
#define MBAR_INIT(a, n) asm volatile("mbarrier.init.shared.b64 [%0], %1;" :: "r"(a), "r"((uint32_t)(n)) : "memory")
#define MBAR_EXPECT_TX(a, n) asm volatile("mbarrier.arrive.expect_tx.shared.b64 _, [%0], %1;" :: "r"(a), "r"((uint32_t)(n)) : "memory")
#define MBAR_ARRIVE(a) asm volatile("mbarrier.arrive.shared.b64 _, [%0];" :: "r"(a) : "memory")

#define MBAR_WAIT(mbar, par) do { \
    uint32_t _m = (mbar); uint32_t _p = (par); uint32_t _d; \
    asm volatile("{ .reg .pred p; mbarrier.try_wait.parity.acquire.cta.shared::cta.b64 p, [%1], %2; selp.b32 %0,1,0,p; }" \
        : "=r"(_d) : "r"(_m), "r"(_p) : "memory"); \
    if (!_d) { \
        asm volatile("{ .reg .pred P1; WL%=: mbarrier.try_wait.parity.acquire.cta.shared::cta.b64 P1, [%0], %1, 0x989680; @P1 bra.uni WD%=; bra.uni WL%=; WD%=: }" \
            :: "r"(_m), "r"(_p) : "memory"); \
    } \
} while (0)

__device__ __forceinline__ void bulk_g2s(uint32_t dst, const void* src, uint32_t bytes, uint32_t mbar) {
    asm volatile("cp.async.bulk.shared::cta.global.mbarrier::complete_tx::bytes [%0], [%1], %2, [%3];"
        :: "r"(dst), "l"(src), "r"(bytes), "r"(mbar) : "memory");
}

__device__ __forceinline__ void ldsm4(uint32_t* r, uint32_t addr) {
    asm volatile("ldmatrix.sync.aligned.m8n8.x4.shared.b16 {%0,%1,%2,%3}, [%4];"
        : "=r"(r[0]), "=r"(r[1]), "=r"(r[2]), "=r"(r[3]) : "r"(addr));
}
__device__ __forceinline__ void mma4(float (&d)[4], const uint32_t* a, uint32_t b0, uint32_t b1) {
    asm volatile("mma.sync.aligned.m16n8k16.row.col.f32.bf16.bf16.f32 "
                 "{%0,%1,%2,%3},{%4,%5,%6,%7},{%8,%9},{%0,%1,%2,%3};"
                 : "+f"(d[0]), "+f"(d[1]), "+f"(d[2]), "+f"(d[3])
                 : "r"(a[0]), "r"(a[1]), "r"(a[2]), "r"(a[3]), "r"(b0), "r"(b1));
}

// ---------------- dtype detection for edge_index ----------------
__global__ void detect_kernel(const unsigned int* ei, int n_scan) {
    __shared__ int nz;
    if (threadIdx.x == 0) nz = 0;
    __syncthreads();
    int loc = 0;
    for (int i = threadIdx.x; i < n_scan; i += blockDim.x)
        if (ei[2 * i + 1] != 0u) loc = 1;
    if (loc) atomicExch(&nz, 1);
    __syncthreads();
    if (threadIdx.x == 0) g_mode64 = (nz == 0) ? 1 : 0;
}

// ---------------- weight prep: bf16 hi/lo, [n][k32-chunk] rows of 64B, XOR swizzle ----------------
// chunk (l,kc): hi block 16KB then lo block 16KB. Row n: 32 bf16 (64B = 4 x 16B). phys c = c ^ ((n>>1)&3).
__global__ void prep_w(const float* __restrict__ W_mid) {
    int idx = blockIdx.x * blockDim.x + threadIdx.x;  // 8*65536
    if (idx >= 8 * 65536) return;
    int l = idx >> 16, rem = idx & 65535, k = rem >> 8, n = rem & 255;
    float w = W_mid[idx];
    __nv_bfloat16 hi = __float2bfloat16(w);
    __nv_bfloat16 lo = __float2bfloat16(w - __bfloat162float(hi));
    int kc = k >> 5, kk = k & 31;
    int c = kk >> 3, phys = c ^ ((n >> 1) & 3);
    size_t off = ((size_t)(l * 8 + kc) * 2) * 16384 + (size_t)n * 64 + phys * 16 + (kk & 7) * 2;
    *(__nv_bfloat16*)(g_WblobB + off) = hi;
    *(__nv_bfloat16*)(g_WblobB + off + 16384) = lo;
}

// ---------------- node kernel (fp32): h = leaky(x@Wx+bx); Pa = h@W0a; Pb = h@W0b ----------------
__global__ __launch_bounds__(256, 1) void node_kernel(
    const float* __restrict__ x, const float* __restrict__ Wx,
    const float* __restrict__ bx, const float* __restrict__ W0, int N)
{
    extern __shared__ float sm[];
    float* Xs = sm;
    float* Hs = Xs + 64 * 256;
    float* Wt = Hs + 64 * 132;

    const int tid = threadIdx.x;
    const int n0 = blockIdx.x * 64;
    {
        const float4* xg = (const float4*)x + (size_t)n0 * 64;
        float4* Xs4 = (float4*)Xs;
#pragma unroll
        for (int i = 0; i < 16; i++) Xs4[tid + 256 * i] = xg[tid + 256 * i];
    }
    __syncthreads();
    {
        const int cg = tid & 15, rg = tid >> 4;
        const int c0 = cg * 8, r0 = rg * 4;
        float acc[4][8];
#pragma unroll
        for (int i = 0; i < 4; i++)
#pragma unroll
            for (int j = 0; j < 8; j++) acc[i][j] = 0.f;
        for (int kc = 0; kc < 256; kc += 16) {
            __syncthreads();
            const float4* wg = (const float4*)(Wx + kc * 128);
            float4* Wt4 = (float4*)Wt;
            Wt4[tid] = wg[tid];
            Wt4[tid + 256] = wg[tid + 256];
            __syncthreads();
#pragma unroll
            for (int k = 0; k < 16; k++) {
                float a[4];
#pragma unroll
                for (int i = 0; i < 4; i++) a[i] = Xs[(r0 + i) * 256 + kc + k];
                float4 w0 = ((float4*)Wt)[k * 32 + cg * 2];
                float4 w1 = ((float4*)Wt)[k * 32 + cg * 2 + 1];
#pragma unroll
                for (int i = 0; i < 4; i++) {
                    float av = a[i];
                    acc[i][0] += av * w0.x; acc[i][1] += av * w0.y;
                    acc[i][2] += av * w0.z; acc[i][3] += av * w0.w;
                    acc[i][4] += av * w1.x; acc[i][5] += av * w1.y;
                    acc[i][6] += av * w1.z; acc[i][7] += av * w1.w;
                }
            }
        }
        float bb[8];
#pragma unroll
        for (int j = 0; j < 8; j++) bb[j] = bx[c0 + j];
#pragma unroll
        for (int i = 0; i < 4; i++) {
            float o[8];
#pragma unroll
            for (int j = 0; j < 8; j++) o[j] = leaky(acc[i][j] + bb[j]);
            *(float4*)(Hs + (r0 + i) * 132 + c0)     = make_float4(o[0], o[1], o[2], o[3]);
            *(float4*)(Hs + (r0 + i) * 132 + c0 + 4) = make_float4(o[4], o[5], o[6], o[7]);
        }
    }
    {
        const int cg = tid & 31, rg = tid >> 5;
        const int c0 = cg * 8, r0 = rg * 8;
#pragma unroll 1
        for (int tab = 0; tab < 2; tab++) {
            const float* Wg = W0 + (size_t)tab * 128 * 256;
            float acc[8][8];
#pragma unroll
            for (int i = 0; i < 8; i++)
#pragma unroll
                for (int j = 0; j < 8; j++) acc[i][j] = 0.f;
            for (int kc = 0; kc < 128; kc += 16) {
                __syncthreads();
                const float4* wg4 = (const float4*)(Wg + kc * 256);
                float4* Wt4 = (float4*)Wt;
#pragma unroll
                for (int i = 0; i < 4; i++) Wt4[tid + 256 * i] = wg4[tid + 256 * i];
                __syncthreads();
#pragma unroll
                for (int k = 0; k < 16; k++) {
                    float a[8];
#pragma unroll
                    for (int i = 0; i < 8; i++) a[i] = Hs[(r0 + i) * 132 + kc + k];
                    float4 w0 = ((float4*)Wt)[k * 64 + cg * 2];
                    float4 w1 = ((float4*)Wt)[k * 64 + cg * 2 + 1];
#pragma unroll
                    for (int i = 0; i < 8; i++) {
                        float av = a[i];
                        acc[i][0] += av * w0.x; acc[i][1] += av * w0.y;
                        acc[i][2] += av * w0.z; acc[i][3] += av * w0.w;
                        acc[i][4] += av * w1.x; acc[i][5] += av * w1.y;
                        acc[i][6] += av * w1.z; acc[i][7] += av * w1.w;
                    }
                }
            }
            float* outp = tab ? g_Pb : g_Pa;
#pragma unroll
            for (int i = 0; i < 8; i++) {
                size_t base = (size_t)(n0 + r0 + i) * 256 + c0;
                *(float4*)(outp + base)     = make_float4(acc[i][0], acc[i][1], acc[i][2], acc[i][3]);
                *(float4*)(outp + base + 4) = make_float4(acc[i][4], acc[i][5], acc[i][6], acc[i][7]);
            }
        }
    }
}

// ================= HMMA edge kernel =================
// 128 edges/CTA, 256 threads (8 warps: 2x4 grid of 64x64 warp tiles — max B-frag reuse).
// A_hi/A_lo fragments stay register-resident across all 3 MMA chains: 16 LDSM per ks-step.
// SMEM: A_hi [128][256]bf16 @0 (64KB), A_lo @65536 (64KB), W stages @131072 (2 x 32KB), misc @196608.
// A row = 512B = 32 x 16B chunks, swizzle: phys = chunk ^ (row&7).
// W chunk rows: [n][k32] 64B, swizzle: phys = c ^ ((n>>1)&3).
#define AH 0
#define AL 65536
#define WS 131072
#define MISC 196608
#define EDGE_SMEM 211968

__global__ __launch_bounds__(256, 1) void edge_kernel(
    const void* __restrict__ ei_raw, const float* __restrict__ edge_attr,
    const float* __restrict__ W0, const float* __restrict__ b0,
    const float* __restrict__ b_mid,
    const float* __restrict__ Wlast, const float* __restrict__ blast,
    float* __restrict__ out, int E)
{
    extern __shared__ char smem[];
    const uint32_t sb = smem_u32(smem);
    const int tid = threadIdx.x, lane = tid & 31, wid = tid >> 5;
    const int wr = wid >> 2, wc = wid & 3;   // 2 rows x 4 cols of warps
    const int e0 = blockIdx.x * 128;

    int* s_row = (int*)(smem + MISC);
    int* s_col = (int*)(smem + MISC + 512);
    const uint32_t mb = sb + MISC + 1024;
    const uint32_t fullb[2] = { mb, mb + 8 };
    const uint32_t freeb[2] = { mb + 16, mb + 24 };
    float* part  = (float*)(smem + MISC + 1536);   // [128][3]
    float* b_all = (float*)(smem + MISC + 4096);   // [8][256]
    float* wl_s  = (float*)(smem + MISC + 12288);  // [256][3]
    float* W0c_s = (float*)(smem + WS + 32768);    // [16][256] (staged in W stage 1, init only)
    float* ea_s  = (float*)(smem + WS + 49152);    // [128][16]

    if (tid == 0) {
        MBAR_INIT(fullb[0], 1); MBAR_INIT(fullb[1], 1);
        MBAR_INIT(freeb[0], 8); MBAR_INIT(freeb[1], 8);
    }
    // ---- stage indices / ea / W0c / biases / Wlast / zero partials ----
    if (tid < 128) {
        long long e = (long long)e0 + tid;
        int r = 0, c = 0;
        if (e < E) {
            if (g_mode64) {
                const long long* p = (const long long*)ei_raw;
                r = (int)p[e]; c = (int)p[(long long)E + e];
            } else {
                const int* p = (const int*)ei_raw;
                r = p[e]; c = p[(long long)E + e];
            }
        }
        s_row[tid] = r; s_col[tid] = c;
    }
    {
        const float4* eg = (const float4*)edge_attr;
        long long base = (long long)e0 * 4;
#pragma unroll
        for (int t = 0; t < 2; t++) {
            long long gi = base + tid + t * 256;
            float4 v = make_float4(0.f, 0.f, 0.f, 0.f);
            if (gi < (long long)E * 4) v = eg[gi];
            ((float4*)ea_s)[tid + t * 256] = v;
        }
        const float4* wg = (const float4*)(W0 + 256 * 256);
#pragma unroll
        for (int t = 0; t < 4; t++) ((float4*)W0c_s)[tid + t * 256] = wg[tid + t * 256];
#pragma unroll
        for (int t = 0; t < 8; t++) b_all[tid + t * 256] = b_mid[tid + t * 256];
#pragma unroll
        for (int t = 0; t < 3; t++) wl_s[tid + t * 256] = Wlast[tid + t * 256];
        if (tid < 192) { part[tid] = 0.f; part[tid + 192] = 0.f; }
    }
    __syncthreads();
    if (tid == 0) {   // prefetch chunk 0 into stage 0 (W0c/ea sit in stage 1)
        MBAR_EXPECT_TX(fullb[0], 32768);
        bulk_g2s(sb + WS, g_WblobB, 32768, fullb[0]);
    }

    // ---- layer-0 init: A(0) = leaky(Pa[row] + Pb[col] + ea@W0c + b0) -> SMEM hi/lo ----
    {
        const int row = tid >> 1, hbase = (tid & 1) * 128;
        const int rn = s_row[row], cn = s_col[row];
        float ear[16];
#pragma unroll
        for (int k = 0; k < 16; k++) ear[k] = ea_s[row * 16 + k];
        const float* pa = g_Pa + (size_t)rn * 256 + hbase;
        const float* pb = g_Pb + (size_t)cn * 256 + hbase;
        const uint32_t rb = row * 512, rx = row & 7;
#pragma unroll 1
        for (int cc = 0; cc < 16; cc++) {
            const int n0 = hbase + cc * 8;
            float v[8];
            float4 A0 = *(const float4*)(pa + cc * 8), A1 = *(const float4*)(pa + cc * 8 + 4);
            float4 B0 = *(const float4*)(pb + cc * 8), B1 = *(const float4*)(pb + cc * 8 + 4);
            v[0] = A0.x + B0.x; v[1] = A0.y + B0.y; v[2] = A0.z + B0.z; v[3] = A0.w + B0.w;
            v[4] = A1.x + B1.x; v[5] = A1.y + B1.y; v[6] = A1.z + B1.z; v[7] = A1.w + B1.w;
#pragma unroll
            for (int k = 0; k < 16; k++) {
                float a = ear[k];
                const float4* wrow = (const float4*)(W0c_s + k * 256 + n0);
                float4 W0v = wrow[0], W1v = wrow[1];
                v[0] += a * W0v.x; v[1] += a * W0v.y; v[2] += a * W0v.z; v[3] += a * W0v.w;
                v[4] += a * W1v.x; v[5] += a * W1v.y; v[6] += a * W1v.z; v[7] += a * W1v.w;
            }
            const uint32_t off = rb + ((((uint32_t)n0 >> 3) ^ rx) << 4);
#pragma unroll
            for (int j = 0; j < 8; j += 2) {
                float v0 = leaky(v[j] + __ldg(&b0[n0 + j]));
                float v1 = leaky(v[j + 1] + __ldg(&b0[n0 + j + 1]));
                __nv_bfloat16 h0 = __float2bfloat16(v0), h1 = __float2bfloat16(v1);
                uint32_t hp = (uint32_t)__bfloat16_as_ushort(h0) | ((uint32_t)__bfloat16_as_ushort(h1) << 16);
                float r0 = v0 - __bfloat162float(h0), r1 = v1 - __bfloat162float(h1);
                __nv_bfloat16 g0 = __float2bfloat16(r0), g1 = __float2bfloat16(r1);
                uint32_t lp = (uint32_t)__bfloat16_as_ushort(g0) | ((uint32_t)__bfloat16_as_ushort(g1) << 16);
                *(uint32_t*)(smem + AH + off + j * 2) = hp;
                *(uint32_t*)(smem + AL + off + j * 2) = lp;
            }
        }
    }
    __syncthreads();
    if (tid == 0) {   // stage 1 free now: prefetch chunk 1
        MBAR_EXPECT_TX(fullb[1], 32768);
        bulk_g2s(sb + WS + 32768, g_WblobB + 32768, 32768, fullb[1]);
    }

    // ---- precomputed fragment addressing ----
    const uint32_t arow = wr * 64 + (lane & 15);
    const uint32_t abase = arow * 512;
    const uint32_t axor = arow & 7;
    const uint32_t akh = lane >> 4;
    const uint32_t bn = wc * 64 + (lane & 15);
    const uint32_t bbase = bn * 64;
    const uint32_t bxor = (bn >> 1) & 3;

    float d[4][8][4];

#pragma unroll 1
    for (int l = 0; l < 8; l++) {
#pragma unroll
        for (int i = 0; i < 4; i++)
#pragma unroll
            for (int j = 0; j < 8; j++)
#pragma unroll
                for (int q = 0; q < 4; q++) d[i][j][q] = 0.f;

#pragma unroll 1
        for (int kc = 0; kc < 8; kc++) {
            const int idx = l * 8 + kc, s = idx & 1, ph = (idx >> 1) & 1;
            MBAR_WAIT(fullb[s], ph);
            const uint32_t wbase = sb + WS + (uint32_t)s * 32768;
#pragma unroll
            for (int ks = 0; ks < 2; ks++) {
                const uint32_t achunk = (uint32_t)kc * 4 + (uint32_t)ks * 2 + akh;
                const uint32_t aoff = ((achunk ^ axor) << 4) + abase;
                const uint32_t c_ = (uint32_t)ks * 2 + akh;
                const uint32_t boff = ((c_ ^ bxor) << 4) + bbase;
                uint32_t afh[4][4], afl[4][4], bfr[4][4];
#pragma unroll
                for (int i = 0; i < 4; i++) ldsm4(afh[i], sb + AH + aoff + i * 8192);       // A_hi
#pragma unroll
                for (int i = 0; i < 4; i++) ldsm4(afl[i], sb + AL + aoff + i * 8192);       // A_lo
#pragma unroll
                for (int g = 0; g < 4; g++) ldsm4(bfr[g], wbase + boff + g * 1024);         // B_hi
#pragma unroll
                for (int i = 0; i < 4; i++)
#pragma unroll
                    for (int g = 0; g < 4; g++) {
                        mma4(d[i][2 * g],     afh[i], bfr[g][0], bfr[g][2]);
                        mma4(d[i][2 * g + 1], afh[i], bfr[g][1], bfr[g][3]);
                    }
#pragma unroll
                for (int i = 0; i < 4; i++)
#pragma unroll
                    for (int g = 0; g < 4; g++) {
                        mma4(d[i][2 * g],     afl[i], bfr[g][0], bfr[g][2]);
                        mma4(d[i][2 * g + 1], afl[i], bfr[g][1], bfr[g][3]);
                    }
#pragma unroll
                for (int g = 0; g < 4; g++) ldsm4(bfr[g], wbase + 16384 + boff + g * 1024); // B_lo
#pragma unroll
                for (int i = 0; i < 4; i++)
#pragma unroll
                    for (int g = 0; g < 4; g++) {
                        mma4(d[i][2 * g],     afh[i], bfr[g][0], bfr[g][2]);
                        mma4(d[i][2 * g + 1], afh[i], bfr[g][1], bfr[g][3]);
                    }
            }
            __syncwarp();
            if (lane == 0) MBAR_ARRIVE(freeb[s]);
            if (tid == 0 && idx + 2 < 64) {
                MBAR_WAIT(freeb[s], ph);
                MBAR_EXPECT_TX(fullb[s], 32768);
                bulk_g2s(sb + WS + (uint32_t)s * 32768,
                         g_WblobB + (size_t)(idx + 2) * 32768, 32768, fullb[s]);
            }
        }

        if (l < 7) {
            // ---- epilogue: A(l+1) = leaky(D + b) -> SMEM hi/lo ----
            __syncthreads();
            const float* bs = b_all + l * 256;
#pragma unroll
            for (int i = 0; i < 4; i++) {
#pragma unroll
                for (int jn = 0; jn < 8; jn++) {
                    const int n = wc * 64 + jn * 8 + 2 * (lane & 3);
                    const float b0v = bs[n], b1v = bs[n + 1];
#pragma unroll
                    for (int h = 0; h < 2; h++) {
                        const int r = wr * 64 + i * 16 + (lane >> 2) + 8 * h;
                        float v0 = leaky(d[i][jn][2 * h]     + b0v);
                        float v1 = leaky(d[i][jn][2 * h + 1] + b1v);
                        __nv_bfloat16 h0 = __float2bfloat16(v0), h1 = __float2bfloat16(v1);
                        uint32_t hp = (uint32_t)__bfloat16_as_ushort(h0) | ((uint32_t)__bfloat16_as_ushort(h1) << 16);
                        float r0 = v0 - __bfloat162float(h0), r1 = v1 - __bfloat162float(h1);
                        __nv_bfloat16 g0 = __float2bfloat16(r0), g1 = __float2bfloat16(r1);
                        uint32_t lp = (uint32_t)__bfloat16_as_ushort(g0) | ((uint32_t)__bfloat16_as_ushort(g1) << 16);
                        const uint32_t off = (uint32_t)r * 512 + (((uint32_t)(n >> 3) ^ (uint32_t)(r & 7)) << 4) + (n & 7) * 2;
                        *(uint32_t*)(smem + AH + off) = hp;
                        *(uint32_t*)(smem + AL + off) = lp;
                    }
                }
            }
            __syncthreads();
        } else {
            // ---- logits: p[c] = sum_n leaky(D + b7[n]) * Wlast[n][c]; quad-shfl + smem atomics ----
            const float* bs = b_all + 7 * 256;
            float p[4][2][3];
#pragma unroll
            for (int i = 0; i < 4; i++)
#pragma unroll
                for (int h = 0; h < 2; h++)
#pragma unroll
                    for (int c = 0; c < 3; c++) p[i][h][c] = 0.f;
#pragma unroll
            for (int jn = 0; jn < 8; jn++) {
                const int n = wc * 64 + jn * 8 + 2 * (lane & 3);
                const float b0v = bs[n], b1v = bs[n + 1];
                const float w00 = wl_s[n * 3 + 0], w01 = wl_s[n * 3 + 1], w02 = wl_s[n * 3 + 2];
                const float w10 = wl_s[(n + 1) * 3 + 0], w11 = wl_s[(n + 1) * 3 + 1], w12 = wl_s[(n + 1) * 3 + 2];
#pragma unroll
                for (int i = 0; i < 4; i++)
#pragma unroll
                    for (int h = 0; h < 2; h++) {
                        float v0 = leaky(d[i][jn][2 * h]     + b0v);
                        float v1 = leaky(d[i][jn][2 * h + 1] + b1v);
                        p[i][h][0] += v0 * w00 + v1 * w10;
                        p[i][h][1] += v0 * w01 + v1 * w11;
                        p[i][h][2] += v0 * w02 + v1 * w12;
                    }
            }
#pragma unroll
            for (int i = 0; i < 4; i++)
#pragma unroll
                for (int h = 0; h < 2; h++)
#pragma unroll
                    for (int c = 0; c < 3; c++) {
                        float val = p[i][h][c];
                        val += __shfl_xor_sync(0xffffffffu, val, 1);
                        val += __shfl_xor_sync(0xffffffffu, val, 2);
                        if ((lane & 3) == 0) {
                            const int r = wr * 64 + i * 16 + (lane >> 2) + 8 * h;
                            atomicAdd(&part[r * 3 + c], val);
                        }
                    }
            __syncthreads();
            if (tid < 128) {
                float l0 = part[tid * 3 + 0] + __ldg(&blast[0]);
                float l1 = part[tid * 3 + 1] + __ldg(&blast[1]);
                float l2 = part[tid * 3 + 2] + __ldg(&blast[2]);
                float m = fmaxf(l0, fmaxf(l1, l2));
                float lse = m + logf(expf(l0 - m) + expf(l1 - m) + expf(l2 - m));
                long long e = (long long)e0 + tid;
                if (e < E) {
                    out[e * 3 + 0] = l0 - lse;
                    out[e * 3 + 1] = l1 - lse;
                    out[e * 3 + 2] = l2 - lse;
                }
            }
        }
    }
}

// ---------------- launch ----------------
extern "C" void kernel_launch(void* const* d_in, const int* in_sizes, int n_in,
                              void* d_out, int out_size)
{
    const float* x         = (const float*)d_in[0];
    const void*  ei        = d_in[1];
    const float* edge_attr = (const float*)d_in[2];
    const float* Wx        = (const float*)d_in[3];
    const float* bx        = (const float*)d_in[4];
    const float* W0        = (const float*)d_in[5];
    const float* b0        = (const float*)d_in[6];
    const float* W_mid     = (const float*)d_in[7];
    const float* b_mid     = (const float*)d_in[8];
    const float* Wlast     = (const float*)d_in[9];
    const float* blast     = (const float*)d_in[10];
    float* out = (float*)d_out;

    const int N = in_sizes[0] / 256;   // node count
    const int E = in_sizes[2] / 16;    // edge count

    const size_t smem_node = (size_t)(64 * 256 + 64 * 132 + 16 * 256) * 4;

    cudaFuncSetAttribute(node_kernel, cudaFuncAttributeMaxDynamicSharedMemorySize, (int)smem_node);
    cudaFuncSetAttribute(edge_kernel, cudaFuncAttributeMaxDynamicSharedMemorySize, EDGE_SMEM);

    int n_scan = E < 2048 ? E : 2048;
    detect_kernel<<<1, 256>>>((const unsigned int*)ei, n_scan);
    prep_w<<<(8 * 65536 + 255) / 256, 256>>>(W_mid);
    node_kernel<<<N / 64, 256, smem_node>>>(x, Wx, bx, W0, N);
    edge_kernel<<<(E + 127) / 128, 256, EDGE_SMEM>>>(ei, edge_attr, W0, b0,
                                                     b_mid, Wlast, blast, out, E);
}